// round 1
// baseline (speedup 1.0000x reference)
#include <cuda_runtime.h>
#include <cuda_bf16.h>
#include <math.h>

// Problem constants
#define BB 64
#define SS 512
#define DD 1024
#define HH 1024
#define TT 9
#define MM (BB * SS)   // 32768 rows

// Scratch: h = input @ W1 + b1  (32768 x 1024 fp32 = 134 MB)
__device__ float g_h[(size_t)MM * HH];
__device__ float g_llh[BB];

// ---------------------------------------------------------------------------
// GEMM1: C[M,H] = A[M,D] @ W1[D,H] + b1   (fp32, 128x128 tile, 8x8/thread)
// ---------------------------------------------------------------------------
#define TILE 128
#define KT 8

__global__ __launch_bounds__(256)
void sgemm1_kernel(const float* __restrict__ A,
                   const float* __restrict__ Bw,
                   const float* __restrict__ bias) {
    __shared__ float As[KT][TILE];
    __shared__ float Bs[KT][TILE];

    const int t  = threadIdx.x;          // 0..255
    const int tx = t & 15;               // 16 cols of threads
    const int ty = t >> 4;               // 16 rows of threads
    const int m0 = blockIdx.y * TILE;
    const int n0 = blockIdx.x * TILE;

    // A-tile load map: 256 threads -> 128 rows x 2 float4 (k)
    const int arow = t >> 1;
    const int ak   = (t & 1) * 4;
    // B-tile load map: 256 threads -> 8 k-rows x 32 float4 (n)
    const int brow = t >> 5;
    const int bn   = (t & 31) * 4;

    float acc[8][8];
    #pragma unroll
    for (int i = 0; i < 8; i++)
        #pragma unroll
        for (int j = 0; j < 8; j++) acc[i][j] = 0.f;

    for (int k0 = 0; k0 < DD; k0 += KT) {
        float4 av = *(const float4*)(A + (size_t)(m0 + arow) * DD + k0 + ak);
        As[ak + 0][arow] = av.x;
        As[ak + 1][arow] = av.y;
        As[ak + 2][arow] = av.z;
        As[ak + 3][arow] = av.w;
        *(float4*)&Bs[brow][bn] =
            *(const float4*)(Bw + (size_t)(k0 + brow) * HH + n0 + bn);
        __syncthreads();

        #pragma unroll
        for (int kk = 0; kk < KT; kk++) {
            float a[8], b[8];
            #pragma unroll
            for (int i = 0; i < 4; i++) {
                ((float4*)a)[0] = *(const float4*)&As[kk][ty * 8];
                ((float4*)a)[1] = *(const float4*)&As[kk][ty * 8 + 4];
                ((float4*)b)[0] = *(const float4*)&Bs[kk][tx * 8];
                ((float4*)b)[1] = *(const float4*)&Bs[kk][tx * 8 + 4];
                break;
            }
            #pragma unroll
            for (int i = 0; i < 8; i++)
                #pragma unroll
                for (int j = 0; j < 8; j++)
                    acc[i][j] += a[i] * b[j];
        }
        __syncthreads();
    }

    #pragma unroll
    for (int i = 0; i < 8; i++) {
        const int m = m0 + ty * 8 + i;
        float* crow = g_h + (size_t)m * HH;
        #pragma unroll
        for (int j = 0; j < 8; j += 4) {
            const int n = n0 + tx * 8 + j;
            float4 v;
            v.x = acc[i][j + 0] + bias[n + 0];
            v.y = acc[i][j + 1] + bias[n + 1];
            v.z = acc[i][j + 2] + bias[n + 2];
            v.w = acc[i][j + 3] + bias[n + 3];
            *(float4*)(crow + n) = v;
        }
    }
}

// ---------------------------------------------------------------------------
// GEMM2: logits[M,9] = h[M,1024] @ W2[1024,9] + b2  (one warp per row)
// ---------------------------------------------------------------------------
__global__ __launch_bounds__(256)
void gemm2_kernel(const float* __restrict__ W2,
                  const float* __restrict__ b2,
                  float* __restrict__ logits) {
    const int row  = blockIdx.x * 8 + (threadIdx.x >> 5);
    const int lane = threadIdx.x & 31;
    const float* hr = g_h + (size_t)row * HH;

    float acc[TT];
    #pragma unroll
    for (int tt = 0; tt < TT; tt++) acc[tt] = 0.f;

    #pragma unroll 4
    for (int i = 0; i < HH / 32; i++) {
        const int k = i * 32 + lane;
        const float a = hr[k];
        const float* w = W2 + k * TT;
        #pragma unroll
        for (int tt = 0; tt < TT; tt++) acc[tt] += a * w[tt];
    }

    float out_v = 0.f;
    #pragma unroll
    for (int tt = 0; tt < TT; tt++) {
        float v = acc[tt];
        #pragma unroll
        for (int o = 16; o > 0; o >>= 1) v += __shfl_xor_sync(0xFFFFFFFFu, v, o);
        if (lane == tt) out_v = v + b2[tt];
    }
    if (lane < TT) logits[(size_t)row * TT + lane] = out_v;
}

// ---------------------------------------------------------------------------
// CRF: per-batch numerator score + forward logsumexp partition
// grid = 64 blocks, 32 threads (one warp)
// ---------------------------------------------------------------------------
__global__ __launch_bounds__(32)
void crf_kernel(const float* __restrict__ logits,
                const int* __restrict__ labels,
                const int* __restrict__ mask,
                const float* __restrict__ start_t,
                const float* __restrict__ end_t,
                const float* __restrict__ trans) {
    const int b    = blockIdx.x;
    const int lane = threadIdx.x;

    __shared__ float tr[TT * TT];
    __shared__ float alpha[2][TT];

    for (int i = lane; i < TT * TT; i += 32) tr[i] = trans[i];
    __syncwarp();

    const float* em = logits + (size_t)b * SS * TT;
    const int*   tg = labels + b * SS;
    const int*   mk = mask + b * SS;

    int   last  = tg[0];
    float score = start_t[last] + em[last];
    if (lane < TT) alpha[0][lane] = start_t[lane] + em[lane];
    __syncwarp();

    int cur = 0;
    for (int s = 1; s < SS; s++) {
        const float* ems = em + s * TT;
        const int   mki  = mk[s];
        const float m_t  = (float)mki;
        const int   tgs  = tg[s];

        // numerator (redundant across lanes, all-broadcast loads)
        score += (tr[last * TT + tgs] + ems[tgs]) * m_t;
        last = (mki != 0) ? tgs : last;

        if (lane < TT) {
            float mx = -INFINITY;
            #pragma unroll
            for (int i = 0; i < TT; i++)
                mx = fmaxf(mx, alpha[cur][i] + tr[i * TT + lane]);
            float sum = 0.f;
            #pragma unroll
            for (int i = 0; i < TT; i++)
                sum += __expf(alpha[cur][i] + tr[i * TT + lane] - mx);
            const float nv = mx + __logf(sum) + ems[lane];
            alpha[1 - cur][lane] = (mki != 0) ? nv : alpha[cur][lane];
        }
        __syncwarp();
        cur = 1 - cur;
    }
    score += end_t[last];

    // log_z = logsumexp(alpha + end)
    const float v  = (lane < TT) ? (alpha[cur][lane] + end_t[lane]) : -INFINITY;
    float mx = v;
    #pragma unroll
    for (int o = 16; o > 0; o >>= 1)
        mx = fmaxf(mx, __shfl_xor_sync(0xFFFFFFFFu, mx, o));
    float e = (lane < TT) ? __expf(v - mx) : 0.f;
    #pragma unroll
    for (int o = 16; o > 0; o >>= 1) e += __shfl_xor_sync(0xFFFFFFFFu, e, o);
    const float log_z = mx + __logf(e);

    if (lane == 0) g_llh[b] = score - log_z;
}

// ---------------------------------------------------------------------------
// Final loss = -mean(llh)
// ---------------------------------------------------------------------------
__global__ __launch_bounds__(32)
void loss_kernel(float* __restrict__ out) {
    const int lane = threadIdx.x;
    float v = g_llh[lane] + g_llh[lane + 32];
    #pragma unroll
    for (int o = 16; o > 0; o >>= 1) v += __shfl_xor_sync(0xFFFFFFFFu, v, o);
    if (lane == 0) out[0] = -(v / (float)BB);
}

// ---------------------------------------------------------------------------
extern "C" void kernel_launch(void* const* d_in, const int* in_sizes, int n_in,
                              void* d_out, int out_size) {
    const float* input   = (const float*)d_in[0];
    const int*   labels  = (const int*)d_in[1];
    const int*   amask   = (const int*)d_in[2];
    const float* W1      = (const float*)d_in[3];
    const float* b1      = (const float*)d_in[4];
    const float* W2      = (const float*)d_in[5];
    const float* b2      = (const float*)d_in[6];
    const float* start_t = (const float*)d_in[7];
    const float* end_t   = (const float*)d_in[8];
    const float* trans   = (const float*)d_in[9];

    float* out    = (float*)d_out;
    float* logits = out + 1;   // layout: [loss, logits(B*S*T)]

    dim3 g1(HH / TILE, MM / TILE);           // (8, 256)
    sgemm1_kernel<<<g1, 256>>>(input, W1, b1);

    gemm2_kernel<<<MM / 8, 256>>>(W2, b2, logits);

    crf_kernel<<<BB, 32>>>(logits, labels, amask, start_t, end_t, trans);

    loss_kernel<<<1, 32>>>(out);
}

// round 2
// speedup vs baseline: 7.6850x; 7.6850x over previous
#include <cuda_runtime.h>
#include <cuda_bf16.h>
#include <math.h>

// Problem constants
#define BB 64
#define SS 512
#define DD 1024
#define HH 1024
#define TT 9
#define MM (BB * SS)   // 32768 rows

// Scratch
__device__ float g_w12t[TT * DD];   // W12 transposed: [t][k]
__device__ float g_b12[TT];
__device__ float g_llh[BB];

// ---------------------------------------------------------------------------
// Kernel A: W12[k,t] = sum_h W1[k,h]*W2[h,t]  (stored transposed [t][k])
//           b12[t]  = sum_h b1[h]*W2[h,t] + b2[t]
// One warp per k-row (1024 rows + 1 bias row = 1025 warps)
// ---------------------------------------------------------------------------
__global__ __launch_bounds__(256)
void w12_kernel(const float* __restrict__ W1,
                const float* __restrict__ b1,
                const float* __restrict__ W2,
                const float* __restrict__ b2) {
    const int warp = (blockIdx.x * 256 + threadIdx.x) >> 5;
    const int lane = threadIdx.x & 31;
    if (warp > DD) return;

    const float* arow = (warp < DD) ? (W1 + (size_t)warp * HH) : b1;

    float acc[TT];
    #pragma unroll
    for (int t = 0; t < TT; t++) acc[t] = 0.f;

    #pragma unroll
    for (int i = 0; i < HH / 128; i++) {
        const int h = i * 128 + lane * 4;
        float4 a = *(const float4*)(arow + h);
        #pragma unroll
        for (int c = 0; c < 4; c++) {
            const float av = (&a.x)[c];
            const float* w = W2 + (size_t)(h + c) * TT;
            #pragma unroll
            for (int t = 0; t < TT; t++) acc[t] += av * w[t];
        }
    }

    float outv = 0.f;
    #pragma unroll
    for (int t = 0; t < TT; t++) {
        float v = acc[t];
        #pragma unroll
        for (int o = 16; o > 0; o >>= 1) v += __shfl_xor_sync(0xFFFFFFFFu, v, o);
        if (lane == t) outv = v;
    }
    if (lane < TT) {
        if (warp < DD) g_w12t[lane * DD + warp] = outv;
        else           g_b12[lane] = outv + b2[lane];
    }
}

// ---------------------------------------------------------------------------
// Kernel B: logits[M,9] = X[M,1024] @ W12 + b12
// W12T in smem ([9][1024], conflict-free float4). 4 rows per warp so the
// smem weight loads amortize. DRAM-bound target: read X once (134 MB).
// ---------------------------------------------------------------------------
#define RPW 4

__global__ __launch_bounds__(256)
void logits_kernel(const float* __restrict__ X,
                   float* __restrict__ logits) {
    __shared__ float sw[TT * DD];   // 36 KB

    {   // cooperative load of W12T
        const float4* src = (const float4*)g_w12t;
        float4* dst = (float4*)sw;
        #pragma unroll
        for (int i = threadIdx.x; i < TT * DD / 4; i += 256) dst[i] = src[i];
    }
    __syncthreads();

    const int warp = threadIdx.x >> 5;
    const int lane = threadIdx.x & 31;
    const int row0 = (blockIdx.x * 8 + warp) * RPW;

    float acc[RPW][TT];
    #pragma unroll
    for (int r = 0; r < RPW; r++)
        #pragma unroll
        for (int t = 0; t < TT; t++) acc[r][t] = 0.f;

    #pragma unroll
    for (int i = 0; i < DD / 128; i++) {
        const int k = i * 128 + lane * 4;
        float4 wv[TT];
        #pragma unroll
        for (int t = 0; t < TT; t++)
            wv[t] = *(const float4*)(sw + t * DD + k);
        #pragma unroll
        for (int r = 0; r < RPW; r++) {
            const float4 xv = *(const float4*)(X + (size_t)(row0 + r) * DD + k);
            #pragma unroll
            for (int t = 0; t < TT; t++) {
                acc[r][t] = fmaf(xv.x, wv[t].x, acc[r][t]);
                acc[r][t] = fmaf(xv.y, wv[t].y, acc[r][t]);
                acc[r][t] = fmaf(xv.z, wv[t].z, acc[r][t]);
                acc[r][t] = fmaf(xv.w, wv[t].w, acc[r][t]);
            }
        }
    }

    #pragma unroll
    for (int r = 0; r < RPW; r++) {
        const int row = row0 + r;
        float outv = 0.f;
        #pragma unroll
        for (int t = 0; t < TT; t++) {
            float v = acc[r][t];
            #pragma unroll
            for (int o = 16; o > 0; o >>= 1) v += __shfl_xor_sync(0xFFFFFFFFu, v, o);
            if (lane == t) outv = v + g_b12[t];
        }
        if (lane < TT) logits[(size_t)row * TT + lane] = outv;
    }
}

// ---------------------------------------------------------------------------
// CRF: register-resident alpha (lane j holds alpha[j]), shuffle broadcast,
// one-step-ahead prefetch of emissions/tags/mask. One warp per batch elem.
// ---------------------------------------------------------------------------
__global__ __launch_bounds__(32)
void crf_kernel(const float* __restrict__ logits,
                const int* __restrict__ labels,
                const int* __restrict__ mask,
                const float* __restrict__ start_t,
                const float* __restrict__ end_t,
                const float* __restrict__ trans) {
    const int b    = blockIdx.x;
    const int lane = threadIdx.x;

    __shared__ float str[TT * TT];
    for (int i = lane; i < TT * TT; i += 32) str[i] = trans[i];

    const int j = (lane < TT) ? lane : 0;
    float trcol[TT];
    #pragma unroll
    for (int i = 0; i < TT; i++) trcol[i] = trans[i * TT + j];
    __syncwarp();

    const float* em = logits + (size_t)b * SS * TT;
    const int*   tg = labels + b * SS;
    const int*   mk = mask + b * SS;

    int   last  = tg[0];
    float score = start_t[last] + em[last];
    float alpha = (lane < TT) ? (start_t[lane] + em[lane]) : -1e30f;

    // prefetch s=1
    float nem = (lane < TT) ? em[TT + lane] : 0.f;
    int   ntg = tg[1];
    int   nmk = mk[1];

    for (int s = 1; s < SS; s++) {
        const float ems = nem;
        const int   tgs = ntg;
        const int   mki = nmk;
        if (s + 1 < SS) {
            nem = (lane < TT) ? em[(s + 1) * TT + lane] : 0.f;
            ntg = tg[s + 1];
            nmk = mk[s + 1];
        }

        // numerator (uniform across lanes)
        const float em_tag = __shfl_sync(0xFFFFFFFFu, ems, tgs);
        if (mki) {
            score += str[last * TT + tgs] + em_tag;
            last = tgs;
        }

        // forward recurrence: new alpha[j] = lse_i(alpha[i] + tr[i][j]) + em[j]
        float terms[TT];
        float mx = -1e30f;
        #pragma unroll
        for (int i = 0; i < TT; i++) {
            const float ai = __shfl_sync(0xFFFFFFFFu, alpha, i);
            terms[i] = ai + trcol[i];
            mx = fmaxf(mx, terms[i]);
        }
        float sum = 0.f;
        #pragma unroll
        for (int i = 0; i < TT; i++) sum += __expf(terms[i] - mx);
        const float nv = mx + __logf(sum) + ems;
        if (mki && lane < TT) alpha = nv;
    }
    score += end_t[last];

    // log_z = lse_j(alpha[j] + end[j])
    const float v = (lane < TT) ? (alpha + end_t[lane]) : -1e30f;
    float mx = v;
    #pragma unroll
    for (int o = 16; o > 0; o >>= 1)
        mx = fmaxf(mx, __shfl_xor_sync(0xFFFFFFFFu, mx, o));
    float e = (lane < TT) ? __expf(v - mx) : 0.f;
    #pragma unroll
    for (int o = 16; o > 0; o >>= 1) e += __shfl_xor_sync(0xFFFFFFFFu, e, o);
    const float log_z = mx + __logf(e);

    if (lane == 0) g_llh[b] = score - log_z;
}

// ---------------------------------------------------------------------------
// Final loss = -mean(llh)
// ---------------------------------------------------------------------------
__global__ __launch_bounds__(32)
void loss_kernel(float* __restrict__ out) {
    const int lane = threadIdx.x;
    float v = g_llh[lane] + g_llh[lane + 32];
    #pragma unroll
    for (int o = 16; o > 0; o >>= 1) v += __shfl_xor_sync(0xFFFFFFFFu, v, o);
    if (lane == 0) out[0] = -(v / (float)BB);
}

// ---------------------------------------------------------------------------
extern "C" void kernel_launch(void* const* d_in, const int* in_sizes, int n_in,
                              void* d_out, int out_size) {
    const float* input   = (const float*)d_in[0];
    const int*   labels  = (const int*)d_in[1];
    const int*   amask   = (const int*)d_in[2];
    const float* W1      = (const float*)d_in[3];
    const float* b1      = (const float*)d_in[4];
    const float* W2      = (const float*)d_in[5];
    const float* b2      = (const float*)d_in[6];
    const float* start_t = (const float*)d_in[7];
    const float* end_t   = (const float*)d_in[8];
    const float* trans   = (const float*)d_in[9];

    float* out    = (float*)d_out;
    float* logits = out + 1;   // layout: [loss, logits(B*S*T)]

    // 1025 warps -> 129 blocks of 8 warps
    w12_kernel<<<129, 256>>>(W1, b1, W2, b2);

    // 32768 rows / (8 warps * 4 rows) = 1024 blocks
    logits_kernel<<<MM / (8 * RPW), 256>>>(input, logits);

    crf_kernel<<<BB, 32>>>(logits, labels, amask, start_t, end_t, trans);

    loss_kernel<<<1, 32>>>(out);
}

// round 3
// speedup vs baseline: 16.8276x; 2.1897x over previous
#include <cuda_runtime.h>
#include <cuda_bf16.h>
#include <math.h>

// Problem constants
#define BB 64
#define SS 512
#define DD 1024
#define HH 1024
#define TT 9
#define MM (BB * SS)   // 32768 rows

// Time-chunking for the CRF scan
#define NC  32         // chunks
#define LCH 16         // steps per chunk (covers s = 1..511)

// Scratch
__device__ float g_w12t[TT * DD];          // W12 transposed: [t][k]
__device__ float g_b12[TT];
__device__ float g_M[(size_t)BB * NC * TT * TT];  // chunk transfer matrices (log domain)
__device__ float g_llh[BB];

// ---------------------------------------------------------------------------
// Kernel A: W12[k,t] = sum_h W1[k,h]*W2[h,t]  (stored transposed [t][k])
//           b12[t]  = sum_h b1[h]*W2[h,t] + b2[t]
// ---------------------------------------------------------------------------
__global__ __launch_bounds__(256)
void w12_kernel(const float* __restrict__ W1,
                const float* __restrict__ b1,
                const float* __restrict__ W2,
                const float* __restrict__ b2) {
    const int warp = (blockIdx.x * 256 + threadIdx.x) >> 5;
    const int lane = threadIdx.x & 31;
    if (warp > DD) return;

    const float* arow = (warp < DD) ? (W1 + (size_t)warp * HH) : b1;

    float acc[TT];
    #pragma unroll
    for (int t = 0; t < TT; t++) acc[t] = 0.f;

    #pragma unroll
    for (int i = 0; i < HH / 128; i++) {
        const int h = i * 128 + lane * 4;
        float4 a = *(const float4*)(arow + h);
        #pragma unroll
        for (int c = 0; c < 4; c++) {
            const float av = (&a.x)[c];
            const float* w = W2 + (size_t)(h + c) * TT;
            #pragma unroll
            for (int t = 0; t < TT; t++) acc[t] += av * w[t];
        }
    }

    float outv = 0.f;
    #pragma unroll
    for (int t = 0; t < TT; t++) {
        float v = acc[t];
        #pragma unroll
        for (int o = 16; o > 0; o >>= 1) v += __shfl_xor_sync(0xFFFFFFFFu, v, o);
        if (lane == t) outv = v;
    }
    if (lane < TT) {
        if (warp < DD) g_w12t[lane * DD + warp] = outv;
        else           g_b12[lane] = outv + b2[lane];
    }
}

// ---------------------------------------------------------------------------
// Kernel B: logits[M,9] = X[M,1024] @ W12 + b12   (DRAM-bound: read X once)
// ---------------------------------------------------------------------------
#define RPW 4

__global__ __launch_bounds__(256)
void logits_kernel(const float* __restrict__ X,
                   float* __restrict__ logits) {
    __shared__ float sw[TT * DD];   // 36 KB

    {
        const float4* src = (const float4*)g_w12t;
        float4* dst = (float4*)sw;
        #pragma unroll
        for (int i = threadIdx.x; i < TT * DD / 4; i += 256) dst[i] = src[i];
    }
    __syncthreads();

    const int warp = threadIdx.x >> 5;
    const int lane = threadIdx.x & 31;
    const int row0 = (blockIdx.x * 8 + warp) * RPW;

    float acc[RPW][TT];
    #pragma unroll
    for (int r = 0; r < RPW; r++)
        #pragma unroll
        for (int t = 0; t < TT; t++) acc[r][t] = 0.f;

    #pragma unroll
    for (int i = 0; i < DD / 128; i++) {
        const int k = i * 128 + lane * 4;
        float4 wv[TT];
        #pragma unroll
        for (int t = 0; t < TT; t++)
            wv[t] = *(const float4*)(sw + t * DD + k);
        #pragma unroll
        for (int r = 0; r < RPW; r++) {
            const float4 xv = *(const float4*)(X + (size_t)(row0 + r) * DD + k);
            #pragma unroll
            for (int t = 0; t < TT; t++) {
                acc[r][t] = fmaf(xv.x, wv[t].x, acc[r][t]);
                acc[r][t] = fmaf(xv.y, wv[t].y, acc[r][t]);
                acc[r][t] = fmaf(xv.z, wv[t].z, acc[r][t]);
                acc[r][t] = fmaf(xv.w, wv[t].w, acc[r][t]);
            }
        }
    }

    #pragma unroll
    for (int r = 0; r < RPW; r++) {
        const int row = row0 + r;
        float outv = 0.f;
        #pragma unroll
        for (int t = 0; t < TT; t++) {
            float v = acc[r][t];
            #pragma unroll
            for (int o = 16; o > 0; o >>= 1) v += __shfl_xor_sync(0xFFFFFFFFu, v, o);
            if (lane == t) outv = v + g_b12[t];
        }
        if (lane < TT) logits[(size_t)row * TT + lane] = outv;
    }
}

// ---------------------------------------------------------------------------
// Kernel C: chunked CRF scan — one warp per (batch, chunk, from-state row).
// Builds log-domain transfer matrix row: M[a][j] over the chunk's steps.
// Uses E = exp(trans) so each step needs only 1 exp + 1 log.
// ---------------------------------------------------------------------------
__global__ __launch_bounds__(256)
void chunk_kernel(const float* __restrict__ logits,
                  const int* __restrict__ mask,
                  const float* __restrict__ trans) {
    const int w    = (blockIdx.x * 256 + threadIdx.x) >> 5;
    const int lane = threadIdx.x & 31;
    const int a  = w % TT;
    const int bc = w / TT;
    const int c  = bc % NC;
    const int b  = bc / NC;

    const int j = (lane < TT) ? lane : 0;
    float Ecol[TT];                       // E[i][j] = exp(tr[i][j]), column j
    #pragma unroll
    for (int i = 0; i < TT; i++) Ecol[i] = __expf(trans[i * TT + j]);

    const float* em = logits + (size_t)b * SS * TT;
    const int*   mk = mask + b * SS;

    const int s0 = c * LCH + 1;
    const int s1 = min(SS - 1, s0 + LCH - 1);

    float v = (lane == a) ? 0.f : -1e30f;

    for (int s = s0; s <= s1; ++s) {
        if (mk[s] > 0) {
            const float e = (lane < TT) ? em[s * TT + lane] : 0.f;
            float mx = v;
            #pragma unroll
            for (int o = 16; o > 0; o >>= 1)
                mx = fmaxf(mx, __shfl_xor_sync(0xFFFFFFFFu, mx, o));
            const float p = __expf(v - mx);
            float sum = 0.f;
            #pragma unroll
            for (int i = 0; i < TT; i++)
                sum += __shfl_sync(0xFFFFFFFFu, p, i) * Ecol[i];
            const float nv = mx + __logf(sum) + e;
            if (lane < TT) v = nv;
        }
    }

    if (lane < TT)
        g_M[(((size_t)b * NC + c) * TT + a) * TT + lane] = v;
}

// ---------------------------------------------------------------------------
// Kernel D: per-batch combine — numerator (lane-parallel over time) +
// denominator (compose alpha0 through the NC chunk matrices).
// ---------------------------------------------------------------------------
__global__ __launch_bounds__(32)
void combine_kernel(const float* __restrict__ logits,
                    const int* __restrict__ labels,
                    const int* __restrict__ mask,
                    const float* __restrict__ start_t,
                    const float* __restrict__ end_t,
                    const float* __restrict__ trans) {
    const int b    = blockIdx.x;
    const int lane = threadIdx.x;

    const float* em = logits + (size_t)b * SS * TT;
    const int*   tg = labels + b * SS;
    const int*   mk = mask + b * SS;

    __shared__ float str[TT * TT];
    for (int i = lane; i < TT * TT; i += 32) str[i] = trans[i];
    __syncwarp();

    // ---------- numerator: lane l handles steps [1+16l .. 16+16l] ----------
    const int tg0 = tg[0];
    float partial = 0.f;
    int first = -1, lastt = -1;
    const int sbeg = 1 + lane * LCH;
    const int send = min(SS - 1, sbeg + LCH - 1);
    for (int s = sbeg; s <= send; ++s) {
        if (mk[s] > 0) {
            const int t = tg[s];
            partial += em[s * TT + t];
            if (lastt >= 0) partial += str[lastt * TT + t];
            else            first = t;
            lastt = t;
        }
    }
    // inclusive scan: last masked tag up to and including this lane (-1 = none)
    int carry = lastt;
    #pragma unroll
    for (int off = 1; off < 32; off <<= 1) {
        const int x = __shfl_up_sync(0xFFFFFFFFu, carry, off);
        if (lane >= off && carry < 0) carry = x;
    }
    int pred = __shfl_up_sync(0xFFFFFFFFu, carry, 1);
    if (lane == 0 || pred < 0) pred = tg0;
    if (first >= 0) partial += str[pred * TT + first];
    #pragma unroll
    for (int o = 16; o > 0; o >>= 1)
        partial += __shfl_xor_sync(0xFFFFFFFFu, partial, o);
    int lastFinal = __shfl_sync(0xFFFFFFFFu, carry, 31);
    if (lastFinal < 0) lastFinal = tg0;
    const float score = start_t[tg0] + em[tg0] + partial + end_t[lastFinal];

    // ---------- denominator: alpha0 composed through chunk matrices ----------
    float alpha = (lane < TT) ? (start_t[lane] + em[lane]) : -1e30f;
    const float* Mb = g_M + (size_t)b * NC * TT * TT;
    for (int c = 0; c < NC; ++c) {
        const float* M = Mb + c * TT * TT;
        float terms[TT];
        float mx = -1e30f;
        #pragma unroll
        for (int i = 0; i < TT; i++) {
            const float ai = __shfl_sync(0xFFFFFFFFu, alpha, i);
            const float m = (lane < TT) ? M[i * TT + lane] : -1e30f;
            terms[i] = ai + m;
            mx = fmaxf(mx, terms[i]);
        }
        float sum = 0.f;
        #pragma unroll
        for (int i = 0; i < TT; i++) sum += __expf(terms[i] - mx);
        const float nv = mx + __logf(sum);
        if (lane < TT) alpha = nv;
    }

    const float v = (lane < TT) ? (alpha + end_t[lane]) : -1e30f;
    float mx = v;
    #pragma unroll
    for (int o = 16; o > 0; o >>= 1)
        mx = fmaxf(mx, __shfl_xor_sync(0xFFFFFFFFu, mx, o));
    float e = (lane < TT) ? __expf(v - mx) : 0.f;
    #pragma unroll
    for (int o = 16; o > 0; o >>= 1) e += __shfl_xor_sync(0xFFFFFFFFu, e, o);
    const float log_z = mx + __logf(e);

    if (lane == 0) g_llh[b] = score - log_z;
}

// ---------------------------------------------------------------------------
// Final loss = -mean(llh)
// ---------------------------------------------------------------------------
__global__ __launch_bounds__(32)
void loss_kernel(float* __restrict__ out) {
    const int lane = threadIdx.x;
    float v = g_llh[lane] + g_llh[lane + 32];
    #pragma unroll
    for (int o = 16; o > 0; o >>= 1) v += __shfl_xor_sync(0xFFFFFFFFu, v, o);
    if (lane == 0) out[0] = -(v / (float)BB);
}

// ---------------------------------------------------------------------------
extern "C" void kernel_launch(void* const* d_in, const int* in_sizes, int n_in,
                              void* d_out, int out_size) {
    const float* input   = (const float*)d_in[0];
    const int*   labels  = (const int*)d_in[1];
    const int*   amask   = (const int*)d_in[2];
    const float* W1      = (const float*)d_in[3];
    const float* b1      = (const float*)d_in[4];
    const float* W2      = (const float*)d_in[5];
    const float* b2      = (const float*)d_in[6];
    const float* start_t = (const float*)d_in[7];
    const float* end_t   = (const float*)d_in[8];
    const float* trans   = (const float*)d_in[9];

    float* out    = (float*)d_out;
    float* logits = out + 1;   // layout: [loss, logits(B*S*T)]

    w12_kernel<<<129, 256>>>(W1, b1, W2, b2);

    logits_kernel<<<MM / (8 * RPW), 256>>>(input, logits);

    // 64 * 32 * 9 = 18432 warps -> 2304 blocks of 8 warps
    chunk_kernel<<<(BB * NC * TT) / 8, 256>>>(logits, amask, trans);

    combine_kernel<<<BB, 32>>>(logits, labels, amask, start_t, end_t, trans);

    loss_kernel<<<1, 32>>>(out);
}

// round 4
// speedup vs baseline: 18.3934x; 1.0931x over previous
#include <cuda_runtime.h>
#include <cuda_bf16.h>
#include <math.h>

// Problem constants
#define BB 64
#define SS 512
#define DD 1024
#define HH 1024
#define TT 9
#define MM (BB * SS)   // 32768 rows

// Time-chunking for the CRF scan
#define NC  16         // chunks
#define LCH 32         // steps per chunk (covers s = 1..511)

// Scratch
__device__ float g_w12t[TT * DD];                 // W12 transposed: [t][k]
__device__ float g_b12[TT];
__device__ float g_M[(size_t)BB * NC * TT * TT];  // chunk transfer matrices (log domain)

// ---------------------------------------------------------------------------
// Kernel A: W12[k,t] = sum_h W1[k,h]*W2[h,t]  (stored transposed [t][k])
//           b12[t]  = sum_h b1[h]*W2[h,t] + b2[t];  also zero out[0]
// ---------------------------------------------------------------------------
__global__ __launch_bounds__(256)
void w12_kernel(const float* __restrict__ W1,
                const float* __restrict__ b1,
                const float* __restrict__ W2,
                const float* __restrict__ b2,
                float* __restrict__ out) {
    if (blockIdx.x == 0 && threadIdx.x == 0) out[0] = 0.f;

    const int warp = (blockIdx.x * 256 + threadIdx.x) >> 5;
    const int lane = threadIdx.x & 31;
    if (warp > DD) return;

    const float* arow = (warp < DD) ? (W1 + (size_t)warp * HH) : b1;

    float acc[TT];
    #pragma unroll
    for (int t = 0; t < TT; t++) acc[t] = 0.f;

    #pragma unroll
    for (int i = 0; i < HH / 128; i++) {
        const int h = i * 128 + lane * 4;
        float4 a = *(const float4*)(arow + h);
        #pragma unroll
        for (int c = 0; c < 4; c++) {
            const float av = (&a.x)[c];
            const float* w = W2 + (size_t)(h + c) * TT;
            #pragma unroll
            for (int t = 0; t < TT; t++) acc[t] += av * w[t];
        }
    }

    float outv = 0.f;
    #pragma unroll
    for (int t = 0; t < TT; t++) {
        float v = acc[t];
        #pragma unroll
        for (int o = 16; o > 0; o >>= 1) v += __shfl_xor_sync(0xFFFFFFFFu, v, o);
        if (lane == t) outv = v;
    }
    if (lane < TT) {
        if (warp < DD) g_w12t[lane * DD + warp] = outv;
        else           g_b12[lane] = outv + b2[lane];
    }
}

// ---------------------------------------------------------------------------
// Kernel B: logits[M,9] = X[M,1024] @ W12 + b12   (DRAM-bound: read X once)
// ---------------------------------------------------------------------------
#define RPW 4

__global__ __launch_bounds__(256)
void logits_kernel(const float* __restrict__ X,
                   float* __restrict__ logits) {
    __shared__ float sw[TT * DD];   // 36 KB

    {
        const float4* src = (const float4*)g_w12t;
        float4* dst = (float4*)sw;
        #pragma unroll
        for (int i = threadIdx.x; i < TT * DD / 4; i += 256) dst[i] = src[i];
    }
    __syncthreads();

    const int warp = threadIdx.x >> 5;
    const int lane = threadIdx.x & 31;
    const int row0 = (blockIdx.x * 8 + warp) * RPW;

    float acc[RPW][TT];
    #pragma unroll
    for (int r = 0; r < RPW; r++)
        #pragma unroll
        for (int t = 0; t < TT; t++) acc[r][t] = 0.f;

    #pragma unroll
    for (int i = 0; i < DD / 128; i++) {
        const int k = i * 128 + lane * 4;
        float4 wv[TT];
        #pragma unroll
        for (int t = 0; t < TT; t++)
            wv[t] = *(const float4*)(sw + t * DD + k);
        #pragma unroll
        for (int r = 0; r < RPW; r++) {
            const float4 xv = *(const float4*)(X + (size_t)(row0 + r) * DD + k);
            #pragma unroll
            for (int t = 0; t < TT; t++) {
                acc[r][t] = fmaf(xv.x, wv[t].x, acc[r][t]);
                acc[r][t] = fmaf(xv.y, wv[t].y, acc[r][t]);
                acc[r][t] = fmaf(xv.z, wv[t].z, acc[r][t]);
                acc[r][t] = fmaf(xv.w, wv[t].w, acc[r][t]);
            }
        }
    }

    #pragma unroll
    for (int r = 0; r < RPW; r++) {
        const int row = row0 + r;
        float outv = 0.f;
        #pragma unroll
        for (int t = 0; t < TT; t++) {
            float v = acc[r][t];
            #pragma unroll
            for (int o = 16; o > 0; o >>= 1) v += __shfl_xor_sync(0xFFFFFFFFu, v, o);
            if (lane == t) outv = v + g_b12[t];
        }
        if (lane < TT) logits[(size_t)row * TT + lane] = outv;
    }
}

// ---------------------------------------------------------------------------
// Kernel C: chunked CRF scan — one warp per (batch, chunk, from-state row).
// Linear-domain streaming: w'[j] = exp(em[j]) * sum_i w[i]*E[i][j],
// E = exp(trans). Rare renorm via warp vote; result written in log domain.
// ---------------------------------------------------------------------------
__global__ __launch_bounds__(256)
void chunk_kernel(const float* __restrict__ logits,
                  const int* __restrict__ mask,
                  const float* __restrict__ trans) {
    const int w    = (blockIdx.x * 256 + threadIdx.x) >> 5;
    const int lane = threadIdx.x & 31;
    const int a  = w % TT;
    const int bc = w / TT;
    const int c  = bc % NC;
    const int b  = bc / NC;

    const int j = (lane < TT) ? lane : 0;
    float Ecol[TT];                       // E[i][j] = exp(tr[i][j]), column j
    #pragma unroll
    for (int i = 0; i < TT; i++) Ecol[i] = __expf(trans[i * TT + j]);

    const float* em = logits + (size_t)b * SS * TT;
    const int*   mk = mask + b * SS;

    const int s0 = c * LCH + 1;
    const int s1 = min(SS - 1, s0 + LCH - 1);

    float wv    = (lane == a) ? 1.f : 0.f;
    float logsc = 0.f;

    for (int s = s0; s <= s1; ++s) {
        if (mk[s] > 0) {
            const float e = (lane < TT) ? __expf(em[s * TT + lane]) : 0.f;
            float sum = 0.f;
            #pragma unroll
            for (int i = 0; i < TT; i++)
                sum = fmaf(__shfl_sync(0xFFFFFFFFu, wv, i), Ecol[i], sum);
            if (lane < TT) wv = sum * e;

            // rare renorm: keep wv within fp32 range
            const bool hi = __any_sync(0xFFFFFFFFu, wv > 1e15f);
            const bool lo = !__any_sync(0xFFFFFFFFu, wv > 1e-15f);
            if (hi || lo) {
                float mx = wv;
                #pragma unroll
                for (int o = 16; o > 0; o >>= 1)
                    mx = fmaxf(mx, __shfl_xor_sync(0xFFFFFFFFu, mx, o));
                wv /= mx;
                logsc += __logf(mx);
            }
        }
    }

    if (lane < TT) {
        const float v = (wv > 0.f) ? (__logf(wv) + logsc) : -1e30f;
        g_M[(((size_t)b * NC + c) * TT + a) * TT + lane] = v;
    }
}

// ---------------------------------------------------------------------------
// Kernel D: per-batch combine — numerator (lane-parallel, prefetched) +
// denominator (alpha0 composed through NC chunk matrices, double-buffered).
// Ends with atomicAdd of -llh/B into out[0].
// ---------------------------------------------------------------------------
#define LNUM 16   // numerator steps per lane (32 lanes * 16 = 512 >= SS-1)

__global__ __launch_bounds__(32)
void combine_kernel(const float* __restrict__ logits,
                    const int* __restrict__ labels,
                    const int* __restrict__ mask,
                    const float* __restrict__ start_t,
                    const float* __restrict__ end_t,
                    const float* __restrict__ trans,
                    float* __restrict__ out) {
    const int b    = blockIdx.x;
    const int lane = threadIdx.x;

    const float* em = logits + (size_t)b * SS * TT;
    const int*   tg = labels + b * SS;
    const int*   mk = mask + b * SS;
    const float* Mb = g_M + (size_t)b * NC * TT * TT;

    __shared__ float str[TT * TT];
    for (int i = lane; i < TT * TT; i += 32) str[i] = trans[i];

    // ---- prefetch chunk-matrix column 0 (double buffer) ----
    float Mcur[TT], Mnxt[TT];
    #pragma unroll
    for (int i = 0; i < TT; i++)
        Mcur[i] = (lane < TT) ? __ldg(Mb + (size_t)i * TT + lane) : -1e30f;

    // ---- numerator: prefetch tags/masks, then independent em gathers ----
    const int tg0 = tg[0];
    int tgs[LNUM], mks[LNUM];
    const int sbeg = 1 + lane * LNUM;
    #pragma unroll
    for (int q = 0; q < LNUM; q++) {
        const int s = min(sbeg + q, SS - 1);
        tgs[q] = tg[s];
        mks[q] = (sbeg + q <= SS - 1) ? mk[s] : 0;
    }
    float emg[LNUM];
    #pragma unroll
    for (int q = 0; q < LNUM; q++)
        emg[q] = __ldg(em + (size_t)min(sbeg + q, SS - 1) * TT + tgs[q]);
    __syncwarp();

    float partial = 0.f;
    int first = -1, lastt = -1;
    #pragma unroll
    for (int q = 0; q < LNUM; q++) {
        if (mks[q] > 0) {
            const int t = tgs[q];
            partial += emg[q];
            if (lastt >= 0) partial += str[lastt * TT + t];
            else            first = t;
            lastt = t;
        }
    }
    // inclusive scan: last masked tag up to and including this lane (-1 = none)
    int carry = lastt;
    #pragma unroll
    for (int off = 1; off < 32; off <<= 1) {
        const int x = __shfl_up_sync(0xFFFFFFFFu, carry, off);
        if (lane >= off && carry < 0) carry = x;
    }
    int pred = __shfl_up_sync(0xFFFFFFFFu, carry, 1);
    if (lane == 0 || pred < 0) pred = tg0;
    if (first >= 0) partial += str[pred * TT + first];
    #pragma unroll
    for (int o = 16; o > 0; o >>= 1)
        partial += __shfl_xor_sync(0xFFFFFFFFu, partial, o);
    int lastFinal = __shfl_sync(0xFFFFFFFFu, carry, 31);
    if (lastFinal < 0) lastFinal = tg0;
    const float score = start_t[tg0] + em[tg0] + partial + end_t[lastFinal];

    // ---- denominator: alpha0 composed through chunk matrices ----
    float alpha = (lane < TT) ? (start_t[lane] + em[lane]) : -1e30f;
    for (int c = 0; c < NC; ++c) {
        if (c + 1 < NC) {
            const float* Mn = Mb + (size_t)(c + 1) * TT * TT;
            #pragma unroll
            for (int i = 0; i < TT; i++)
                Mnxt[i] = (lane < TT) ? __ldg(Mn + (size_t)i * TT + lane) : -1e30f;
        }
        float terms[TT];
        #pragma unroll
        for (int i = 0; i < TT; i++)
            terms[i] = __shfl_sync(0xFFFFFFFFu, alpha, i) + Mcur[i];
        float mx = terms[0];
        #pragma unroll
        for (int i = 1; i < TT; i++) mx = fmaxf(mx, terms[i]);
        float sum = 0.f;
        #pragma unroll
        for (int i = 0; i < TT; i++) sum += __expf(terms[i] - mx);
        if (lane < TT) alpha = mx + __logf(sum);
        #pragma unroll
        for (int i = 0; i < TT; i++) Mcur[i] = Mnxt[i];
    }

    const float v = (lane < TT) ? (alpha + end_t[lane]) : -1e30f;
    float mx = v;
    #pragma unroll
    for (int o = 16; o > 0; o >>= 1)
        mx = fmaxf(mx, __shfl_xor_sync(0xFFFFFFFFu, mx, o));
    float e = (lane < TT) ? __expf(v - mx) : 0.f;
    #pragma unroll
    for (int o = 16; o > 0; o >>= 1) e += __shfl_xor_sync(0xFFFFFFFFu, e, o);
    const float log_z = mx + __logf(e);

    if (lane == 0)
        atomicAdd(out, -(score - log_z) * (1.f / (float)BB));
}

// ---------------------------------------------------------------------------
extern "C" void kernel_launch(void* const* d_in, const int* in_sizes, int n_in,
                              void* d_out, int out_size) {
    const float* input   = (const float*)d_in[0];
    const int*   labels  = (const int*)d_in[1];
    const int*   amask   = (const int*)d_in[2];
    const float* W1      = (const float*)d_in[3];
    const float* b1      = (const float*)d_in[4];
    const float* W2      = (const float*)d_in[5];
    const float* b2      = (const float*)d_in[6];
    const float* start_t = (const float*)d_in[7];
    const float* end_t   = (const float*)d_in[8];
    const float* trans   = (const float*)d_in[9];

    float* out    = (float*)d_out;
    float* logits = out + 1;   // layout: [loss, logits(B*S*T)]

    w12_kernel<<<129, 256>>>(W1, b1, W2, b2, out);

    logits_kernel<<<MM / (8 * RPW), 256>>>(input, logits);

    // 64 * 16 * 9 = 9216 warps -> 1152 blocks of 8 warps
    chunk_kernel<<<(BB * NC * TT) / 8, 256>>>(logits, amask, trans);

    combine_kernel<<<BB, 32>>>(logits, labels, amask, start_t, end_t, trans, out);
}